// round 1
// baseline (speedup 1.0000x reference)
#include <cuda_runtime.h>
#include <cstddef>

// Problem geometry (fixed by the reference):
//   256 graphs x 64 nodes -> 4096 edge-rows per graph, E = 1048576, C = 64.
//   Row r = b*4096 + i*64 + j  (complete lexicographic pair set).
//
// Pipeline:
//   K1: X = SP@W4^T/64, Y = SP@W5^T/64, stored CHANNEL-MAJOR: g_Xt[(b*64+c)*4096 + i*64+k]
//   K2: per (b,c): prod = Xc[64x64] @ Yc[64x64], stored channel-major g_prod
//   K3: out = relu(SP@W6a^T + prod@W6b^T), transposing prod back via SMEM tiles.

__device__ float g_Xt[67108864];    // 256 MB scratch: [b][c][i*64+k]
__device__ float g_Yt[67108864];    // 256 MB scratch: [b][c][k*64+j]
__device__ float g_prod[67108864];  // 256 MB scratch: [b][c][i*64+j]

// ---------------------------------------------------------------------------
// K1: fused X/Y GEMM. Tile = 256 rows x 128 outputs (64 X-ch + 64 Y-ch).
// 256 threads: warp w owns 16 channels, lane owns rows {l, l+32, ..., l+224}.
// SMEM: Ws[64][128] (W4^T|W5^T interleaved by channel), SPs[256][65] (pad 65 ->
// bank = (lane + kk) % 32, conflict-free). Epilogue writes are 128B coalesced
// per (channel,d) store into the channel-major scratch.
// ---------------------------------------------------------------------------
__global__ __launch_bounds__(256) void k1_xy(const float* __restrict__ SP,
                                             const float* __restrict__ W4,
                                             const float* __restrict__ W5) {
    extern __shared__ float sm[];
    float* Ws  = sm;              // [64][128]  Ws[m*128+c]
    float* SPs = sm + 64 * 128;   // [256][65]

    const int tid  = threadIdx.x;
    const int row0 = blockIdx.x * 256;   // global row of this tile (graph-aligned)

    // Load weights transposed: Ws[m][c] = W4[c][m] (c<64) / W5[c-64][m]
    for (int idx = tid; idx < 64 * 64; idx += 256) {
        int c = idx >> 6, m = idx & 63;      // idx = c*64 + m
        Ws[m * 128 + c]      = W4[idx];
        Ws[m * 128 + 64 + c] = W5[idx];
    }
    // Load SP tile [256 x 64] (fully coalesced float4)
    const float4* SPg = (const float4*)(SP + (size_t)row0 * 64);
    for (int idx = tid; idx < 256 * 16; idx += 256) {
        float4 v = SPg[idx];
        int r = idx >> 4, m4 = (idx & 15) * 4;
        float* d = &SPs[r * 65 + m4];
        d[0] = v.x; d[1] = v.y; d[2] = v.z; d[3] = v.w;
    }
    __syncthreads();

    const int lane = tid & 31, warp = tid >> 5;
    const int c0 = warp * 16;

    float acc[8][16];
#pragma unroll
    for (int d = 0; d < 8; d++)
#pragma unroll
        for (int cc = 0; cc < 16; cc++) acc[d][cc] = 0.f;

#pragma unroll 2
    for (int kk = 0; kk < 64; kk++) {
        float a[8];
#pragma unroll
        for (int d = 0; d < 8; d++) a[d] = SPs[(lane + 32 * d) * 65 + kk];
        float w[16];
#pragma unroll
        for (int q = 0; q < 4; q++) {
            float4 wv = *(const float4*)&Ws[kk * 128 + c0 + q * 4];
            w[q * 4 + 0] = wv.x; w[q * 4 + 1] = wv.y;
            w[q * 4 + 2] = wv.z; w[q * 4 + 3] = wv.w;
        }
#pragma unroll
        for (int d = 0; d < 8; d++)
#pragma unroll
            for (int cc = 0; cc < 16; cc++)
                acc[d][cc] = fmaf(a[d], w[cc], acc[d][cc]);
    }

    const int b   = row0 >> 12;    // graph id (tiles never cross graphs: 4096 % 256 == 0)
    const int rig = row0 & 4095;   // row within graph
    const float s = 1.0f / 64.0f;
#pragma unroll
    for (int cc = 0; cc < 16; cc++) {
        int c = c0 + cc;
        float* dst = (c < 64)
            ? &g_Xt[(size_t)(b * 64 + c) * 4096 + rig]
            : &g_Yt[(size_t)(b * 64 + (c - 64)) * 4096 + rig];
#pragma unroll
        for (int d = 0; d < 8; d++)
            dst[lane + 32 * d] = acc[d][cc] * s;
    }
}

// ---------------------------------------------------------------------------
// K2: one CTA per (b,c) pair: prod_bc[64x64] = Xc[i][k] @ Yc[k][j].
// Inputs/outputs are contiguous 16KB blocks in the channel-major scratch.
// Thread tile 4x4; A-loads are half-warp broadcasts, B-loads float4 (pad 68
// keeps 16B alignment and spreads banks).
// ---------------------------------------------------------------------------
__global__ __launch_bounds__(256) void k2_bmm() {
    __shared__ float As[64 * 68];
    __shared__ float Bs[64 * 68];
    const int bc = blockIdx.x;           // b*64 + c
    const size_t base = (size_t)bc * 4096;
    const int tid = threadIdx.x;

    const float4* Ag = (const float4*)(g_Xt + base);
    const float4* Bg = (const float4*)(g_Yt + base);
    for (int idx = tid; idx < 1024; idx += 256) {
        int r = idx >> 4, m4 = (idx & 15) * 4;   // 68*4=272 bytes/row -> 16B aligned
        *(float4*)&As[r * 68 + m4] = Ag[idx];
        *(float4*)&Bs[r * 68 + m4] = Bg[idx];
    }
    __syncthreads();

    const int jIdx = tid & 15, iIdx = tid >> 4;
    const int i0 = iIdx * 4, j0 = jIdx * 4;
    float acc[4][4] = {};
#pragma unroll 8
    for (int k = 0; k < 64; k++) {
        float a[4];
#pragma unroll
        for (int d = 0; d < 4; d++) a[d] = As[(i0 + d) * 68 + k];
        float4 bv = *(const float4*)&Bs[k * 68 + j0];
        float bb[4] = {bv.x, bv.y, bv.z, bv.w};
#pragma unroll
        for (int d = 0; d < 4; d++)
#pragma unroll
            for (int e = 0; e < 4; e++)
                acc[d][e] = fmaf(a[d], bb[e], acc[d][e]);
    }
#pragma unroll
    for (int d = 0; d < 4; d++) {
        float4 v = make_float4(acc[d][0], acc[d][1], acc[d][2], acc[d][3]);
        *(float4*)&g_prod[base + (size_t)(i0 + d) * 64 + j0] = v;
    }
}

// ---------------------------------------------------------------------------
// K3: one CTA per (b,i): 64 rows (all j), all 64 out channels.
// out[r] = relu( SP[r]@W6a^T + prod[r]@W6b^T ).  prod arrives channel-major;
// Ps[c][j] is loaded with 256B-coalesced reads and consumed directly (the
// "transpose" is free: second GEMM loop indexes Ps[m][j]).
// ---------------------------------------------------------------------------
__global__ __launch_bounds__(256) void k3_out(const float* __restrict__ SP,
                                              const float* __restrict__ W6,
                                              float* __restrict__ out) {
    extern __shared__ float sm[];
    float* W6s = sm;               // [128][64]  W6s[m*64+c] = W6[c*128+m]
    float* SPs = sm + 128 * 64;    // [64][68]   SPs[j][m]
    float* Ps  = SPs + 64 * 68;    // [64][68]   Ps[c][j]

    const int bi = blockIdx.x;     // b*64 + i
    const int b = bi >> 6, i = bi & 63;
    const int tid = threadIdx.x;

    for (int idx = tid; idx < 64 * 128; idx += 256) {
        int c = idx >> 7, m = idx & 127;         // idx = c*128 + m
        W6s[m * 64 + c] = W6[idx];
    }
    const float4* SPg = (const float4*)(SP + (size_t)bi * 4096);  // 64 rows x 64
    for (int idx = tid; idx < 1024; idx += 256) {
        int r = idx >> 4, m4 = (idx & 15) * 4;
        *(float4*)&SPs[r * 68 + m4] = SPg[idx];
    }
    for (int idx = tid; idx < 1024; idx += 256) {
        int c = idx >> 4, j4 = (idx & 15) * 4;
        float4 v = *(const float4*)&g_prod[(size_t)(b * 64 + c) * 4096 + i * 64 + j4];
        *(float4*)&Ps[c * 68 + j4] = v;
    }
    __syncthreads();

    const int cIdx = tid & 15, jIdx = tid >> 4;
    const int c0 = cIdx * 4, j0 = jIdx * 4;
    float acc[4][4] = {};

    // m in [0,64): SP half
#pragma unroll 8
    for (int m = 0; m < 64; m++) {
        float a[4];
#pragma unroll
        for (int d = 0; d < 4; d++) a[d] = SPs[(j0 + d) * 68 + m];
        float4 wv = *(const float4*)&W6s[m * 64 + c0];
        float w[4] = {wv.x, wv.y, wv.z, wv.w};
#pragma unroll
        for (int d = 0; d < 4; d++)
#pragma unroll
            for (int e = 0; e < 4; e++)
                acc[d][e] = fmaf(a[d], w[e], acc[d][e]);
    }
    // m in [64,128): prod half (Ps is [channel][j], read row m-64 directly)
#pragma unroll 8
    for (int m = 0; m < 64; m++) {
        float4 av = *(const float4*)&Ps[m * 68 + j0];
        float a[4] = {av.x, av.y, av.z, av.w};
        float4 wv = *(const float4*)&W6s[(64 + m) * 64 + c0];
        float w[4] = {wv.x, wv.y, wv.z, wv.w};
#pragma unroll
        for (int d = 0; d < 4; d++)
#pragma unroll
            for (int e = 0; e < 4; e++)
                acc[d][e] = fmaf(a[d], w[e], acc[d][e]);
    }

    float* ob = out + (size_t)bi * 4096;   // rows (bi*64 + j), 64 ch each
#pragma unroll
    for (int d = 0; d < 4; d++) {
        float4 v;
        v.x = fmaxf(acc[d][0], 0.f);
        v.y = fmaxf(acc[d][1], 0.f);
        v.z = fmaxf(acc[d][2], 0.f);
        v.w = fmaxf(acc[d][3], 0.f);
        *(float4*)&ob[(j0 + d) * 64 + c0] = v;
    }
}

// ---------------------------------------------------------------------------
extern "C" void kernel_launch(void* const* d_in, const int* in_sizes, int n_in,
                              void* d_out, int out_size) {
    // Inputs (metadata order): edge_index[2*E] i32, SP[E*64], W4[64*64],
    // W5[64*64], W6[64*128]. edge_index is the deterministic complete pair
    // set and is not needed. Map defensively by element count.
    const float* SP = nullptr;
    const float* W4 = nullptr;
    const float* W5 = nullptr;
    const float* W6 = nullptr;
    for (int idx = 0; idx < n_in; idx++) {
        int sz = in_sizes[idx];
        if (sz == 67108864)      SP = (const float*)d_in[idx];
        else if (sz == 8192)     W6 = (const float*)d_in[idx];
        else if (sz == 4096) {
            if (!W4) W4 = (const float*)d_in[idx];
            else     W5 = (const float*)d_in[idx];
        }
    }
    float* out = (float*)d_out;

    const int smem1 = (64 * 128 + 256 * 65) * 4;        // 99328 B
    const int smem3 = (128 * 64 + 2 * 64 * 68) * 4;     // 67584 B
    cudaFuncSetAttribute(k1_xy,  cudaFuncAttributeMaxDynamicSharedMemorySize, smem1);
    cudaFuncSetAttribute(k3_out, cudaFuncAttributeMaxDynamicSharedMemorySize, smem3);

    k1_xy <<<4096,  256, smem1>>>(SP, W4, W5);
    k2_bmm<<<16384, 256>>>();
    k3_out<<<16384, 256, smem3>>>(SP, W6, out);
}

// round 4
// speedup vs baseline: 1.4478x; 1.4478x over previous
#include <cuda_runtime.h>
#include <cuda_bf16.h>
#include <cstdint>
#include <cstddef>

// 256 graphs x 64 nodes; E=1048576 rows (r = b*4096 + i*64 + j); C=64.
// K1: X=SP@W4^T/64, Y=SP@W5^T/64 -> channel-major scratch [b*64+c][4096]
// K2: per (b, channel-pair): prod_c = X_c @ Y_c   (diagonal blocks only)
// K3: out = relu(SP@W6a^T + prod@W6b^T)
// Tensor path: mma.sync m16n8k16 bf16 (sm_100-legal), 3-term bf16 split:
//   A = [hi|hi|lo], B = [hi|lo|hi] along K  =>  hi*hi + hi*lo + lo*hi  (~1e-5 rel)

__device__ float g_Xt[67108864];
__device__ float g_Yt[67108864];
__device__ float g_prod[67108864];

#define AK  200   // bf16 col-stride for A and K1/K2 B tiles (192 data + 8 pad)
#define BK3 408   // K3 B stride: two 200-wide halves + pad

__device__ __forceinline__ void splitb(float v, unsigned short& h, unsigned short& l) {
    __nv_bfloat16 hb = __float2bfloat16_rn(v);
    float r = v - __bfloat162float(hb);
    __nv_bfloat16 lb = __float2bfloat16_rn(r);
    h = reinterpret_cast<unsigned short&>(hb);
    l = reinterpret_cast<unsigned short&>(lb);
}
__device__ __forceinline__ uint32_t ld2(const unsigned short* p, int idx) {
    return *reinterpret_cast<const uint32_t*>(p + idx);   // idx always even
}
__device__ __forceinline__ void mma16(float* c, uint32_t a0, uint32_t a1, uint32_t a2, uint32_t a3,
                                      uint32_t b0, uint32_t b1) {
    asm volatile("mma.sync.aligned.m16n8k16.row.col.f32.bf16.bf16.f32 "
                 "{%0,%1,%2,%3},{%4,%5,%6,%7},{%8,%9},{%0,%1,%2,%3};"
                 : "+f"(c[0]), "+f"(c[1]), "+f"(c[2]), "+f"(c[3])
                 : "r"(a0), "r"(a1), "r"(a2), "r"(a3), "r"(b0), "r"(b1));
}

// ===================== K1: X|Y = SP @ [W4|W5]^T / 64 =====================
__global__ __launch_bounds__(256) void k1(const float* __restrict__ SP,
                                          const float* __restrict__ W4,
                                          const float* __restrict__ W5) {
    extern __shared__ char smraw[];
    unsigned short* As = (unsigned short*)smraw;      // [128][AK]
    unsigned short* Bs = As + 128 * AK;               // [128][AK]
    const int tid = threadIdx.x;
    const int row0 = blockIdx.x * 128;
    const int b = row0 >> 12, rig = row0 & 4095;

    const float4* SPg = (const float4*)(SP + (size_t)row0 * 64);
#pragma unroll
    for (int it = 0; it < 8; it++) {
        int idx = tid + it * 256;
        float4 v = SPg[idx];
        int r = idx >> 4, k0 = (idx & 15) * 4;
        float e[4] = {v.x, v.y, v.z, v.w};
#pragma unroll
        for (int q = 0; q < 4; q++) {
            unsigned short h, l; splitb(e[q], h, l);
            int k = k0 + q;
            As[r * AK + k] = h; As[r * AK + 64 + k] = h; As[r * AK + 128 + k] = l;
        }
    }
#pragma unroll
    for (int it = 0; it < 8; it++) {
        int idx = tid + it * 256;
        int n = idx >> 4, k0 = (idx & 15) * 4;
        float4 v = (n < 64) ? ((const float4*)W4)[idx] : ((const float4*)W5)[idx - 1024];
        float e[4] = {v.x, v.y, v.z, v.w};
#pragma unroll
        for (int q = 0; q < 4; q++) {
            unsigned short h, l; splitb(e[q], h, l);
            int k = k0 + q;
            Bs[n * AK + k] = h; Bs[n * AK + 64 + k] = l; Bs[n * AK + 128 + k] = h;
        }
    }
    __syncthreads();

    const int warp = tid >> 5, lane = tid & 31;
    const int g = lane >> 2, t2 = (lane & 3) * 2;
    const int mr = (warp >> 2) * 64, nc = (warp & 3) * 32;
    float acc[4][4][4];
#pragma unroll
    for (int mt = 0; mt < 4; mt++)
#pragma unroll
        for (int nt = 0; nt < 4; nt++)
#pragma unroll
            for (int q = 0; q < 4; q++) acc[mt][nt][q] = 0.f;

#pragma unroll
    for (int kt = 0; kt < 12; kt++) {
        const int kk = kt * 16;
        uint32_t a[4][4];
#pragma unroll
        for (int mt = 0; mt < 4; mt++) {
            int rb = mr + mt * 16 + g;
            a[mt][0] = ld2(As, rb * AK + kk + t2);
            a[mt][1] = ld2(As, (rb + 8) * AK + kk + t2);
            a[mt][2] = ld2(As, rb * AK + kk + 8 + t2);
            a[mt][3] = ld2(As, (rb + 8) * AK + kk + 8 + t2);
        }
        uint32_t bb[4][2];
#pragma unroll
        for (int nt = 0; nt < 4; nt++) {
            int n = nc + nt * 8 + g;
            bb[nt][0] = ld2(Bs, n * AK + kk + t2);
            bb[nt][1] = ld2(Bs, n * AK + kk + 8 + t2);
        }
#pragma unroll
        for (int mt = 0; mt < 4; mt++)
#pragma unroll
            for (int nt = 0; nt < 4; nt++)
                mma16(acc[mt][nt], a[mt][0], a[mt][1], a[mt][2], a[mt][3], bb[nt][0], bb[nt][1]);
    }
    __syncthreads();

    float* Ds = (float*)smraw;                        // [128 c][132]
#pragma unroll
    for (int mt = 0; mt < 4; mt++)
#pragma unroll
        for (int nt = 0; nt < 4; nt++) {
            int row = mr + mt * 16 + g;
            int col = nc + nt * 8 + t2;
            Ds[col * 132 + row]           = acc[mt][nt][0] * 0.015625f;
            Ds[(col + 1) * 132 + row]     = acc[mt][nt][1] * 0.015625f;
            Ds[col * 132 + row + 8]       = acc[mt][nt][2] * 0.015625f;
            Ds[(col + 1) * 132 + row + 8] = acc[mt][nt][3] * 0.015625f;
        }
    __syncthreads();
#pragma unroll
    for (int it = 0; it < 64; it++) {
        int idx = tid + it * 256;
        int c = idx >> 7, m = idx & 127;
        float val = Ds[c * 132 + m];
        if (c < 64) g_Xt[((size_t)(b * 64 + c)) * 4096 + rig + m] = val;
        else        g_Yt[((size_t)(b * 64 + c - 64)) * 4096 + rig + m] = val;
    }
}

// ===================== K2: prod_c = X_c @ Y_c (2 channels / CTA) =====================
__global__ __launch_bounds__(256) void k2() {
    extern __shared__ char smraw[];
    unsigned short* As = (unsigned short*)smraw;      // [128][AK]  [X_c1; X_c2]
    unsigned short* Bs = As + 128 * AK;               // [128][AK]  [Y_c1^T; Y_c2^T]
    const int tid = threadIdx.x;
    const int b = blockIdx.x >> 5, c1 = (blockIdx.x & 31) * 2;
    const size_t base = ((size_t)(b * 64 + c1)) * 4096;

    const float4* Xg = (const float4*)(g_Xt + base);
#pragma unroll
    for (int it = 0; it < 8; it++) {
        int idx = tid + it * 256;
        float4 v = Xg[idx];
        int e0 = idx * 4;
        int k0 = e0 & 63, m = (e0 >> 12) * 64 + ((e0 >> 6) & 63);
        float e[4] = {v.x, v.y, v.z, v.w};
#pragma unroll
        for (int q = 0; q < 4; q++) {
            unsigned short h, l; splitb(e[q], h, l);
            int k = k0 + q;
            As[m * AK + k] = h; As[m * AK + 64 + k] = h; As[m * AK + 128 + k] = l;
        }
    }
    const float4* Yg = (const float4*)(g_Yt + base);
#pragma unroll
    for (int it = 0; it < 8; it++) {
        int idx = tid + it * 256;
        float4 v = Yg[idx];
        int e0 = idx * 4;
        int j0 = e0 & 63, kq = (e0 >> 6) & 63, cid = e0 >> 12;
        float e[4] = {v.x, v.y, v.z, v.w};
#pragma unroll
        for (int q = 0; q < 4; q++) {           // transpose: B[n=j][k]
            unsigned short h, l; splitb(e[q], h, l);
            int n = cid * 64 + j0 + q;
            Bs[n * AK + kq] = h; Bs[n * AK + 64 + kq] = l; Bs[n * AK + 128 + kq] = h;
        }
    }
    __syncthreads();

    const int warp = tid >> 5, lane = tid & 31;
    const int g = lane >> 2, t2 = (lane & 3) * 2;
    const int hh = warp >> 2;                         // which channel of the pair
    const int mr = hh * 64, nc = hh * 64 + (warp & 3) * 16;
    float acc[4][2][4];
#pragma unroll
    for (int mt = 0; mt < 4; mt++)
#pragma unroll
        for (int nt = 0; nt < 2; nt++)
#pragma unroll
            for (int q = 0; q < 4; q++) acc[mt][nt][q] = 0.f;

#pragma unroll
    for (int kt = 0; kt < 12; kt++) {
        const int kk = kt * 16;
        uint32_t a[4][4];
#pragma unroll
        for (int mt = 0; mt < 4; mt++) {
            int rb = mr + mt * 16 + g;
            a[mt][0] = ld2(As, rb * AK + kk + t2);
            a[mt][1] = ld2(As, (rb + 8) * AK + kk + t2);
            a[mt][2] = ld2(As, rb * AK + kk + 8 + t2);
            a[mt][3] = ld2(As, (rb + 8) * AK + kk + 8 + t2);
        }
        uint32_t bb[2][2];
#pragma unroll
        for (int nt = 0; nt < 2; nt++) {
            int n = nc + nt * 8 + g;
            bb[nt][0] = ld2(Bs, n * AK + kk + t2);
            bb[nt][1] = ld2(Bs, n * AK + kk + 8 + t2);
        }
#pragma unroll
        for (int mt = 0; mt < 4; mt++)
#pragma unroll
            for (int nt = 0; nt < 2; nt++)
                mma16(acc[mt][nt], a[mt][0], a[mt][1], a[mt][2], a[mt][3], bb[nt][0], bb[nt][1]);
    }
    __syncthreads();

    float* Ds = (float*)smraw;                        // [128 rows][68]
#pragma unroll
    for (int mt = 0; mt < 4; mt++)
#pragma unroll
        for (int nt = 0; nt < 2; nt++) {
            int row = mr + mt * 16 + g;
            int jl = (warp & 3) * 16 + nt * 8 + t2;   // local col within channel
            Ds[row * 68 + jl]           = acc[mt][nt][0];
            Ds[row * 68 + jl + 1]       = acc[mt][nt][1];
            Ds[(row + 8) * 68 + jl]     = acc[mt][nt][2];
            Ds[(row + 8) * 68 + jl + 1] = acc[mt][nt][3];
        }
    __syncthreads();
#pragma unroll
    for (int it = 0; it < 32; it++) {
        int idx = tid + it * 256;                     // cid*4096 + i*64 + j
        g_prod[base + idx] = Ds[(idx >> 6) * 68 + (idx & 63)];
    }
}

// ===================== K3: out = relu(SP@W6a^T + prod@W6b^T) =====================
__global__ __launch_bounds__(256) void k3(const float* __restrict__ SP,
                                          const float* __restrict__ W6,
                                          float* __restrict__ out) {
    extern __shared__ char smraw[];
    unsigned short* As = (unsigned short*)smraw;      // [128][AK]
    unsigned short* Bs = As + 128 * AK;               // [64][BK3]
    const int tid = threadIdx.x;
    const int row0 = blockIdx.x * 128;
    const int b = row0 >> 12, rig = row0 & 4095;

    // A pass1 = SP rows
    const float4* SPg = (const float4*)(SP + (size_t)row0 * 64);
#pragma unroll
    for (int it = 0; it < 8; it++) {
        int idx = tid + it * 256;
        float4 v = SPg[idx];
        int r = idx >> 4, k0 = (idx & 15) * 4;
        float e[4] = {v.x, v.y, v.z, v.w};
#pragma unroll
        for (int q = 0; q < 4; q++) {
            unsigned short h, l; splitb(e[q], h, l);
            int k = k0 + q;
            As[r * AK + k] = h; As[r * AK + 64 + k] = h; As[r * AK + 128 + k] = l;
        }
    }
    // B: both halves of W6  (half s at col-offset 0 / 200)
#pragma unroll
    for (int it = 0; it < 8; it++) {
        int idx = tid + it * 256;                     // 2048 float4 = 64 rows x 32
        int o = idx >> 5, m0 = (idx & 31) * 4;
        float4 v = ((const float4*)W6)[idx];
        float e[4] = {v.x, v.y, v.z, v.w};
#pragma unroll
        for (int q = 0; q < 4; q++) {
            unsigned short h, l; splitb(e[q], h, l);
            int m = m0 + q;
            int s = (m < 64) ? 0 : 200;
            int k = m & 63;
            Bs[o * BK3 + s + k] = h; Bs[o * BK3 + s + 64 + k] = l; Bs[o * BK3 + s + 128 + k] = h;
        }
    }
    __syncthreads();

    const int warp = tid >> 5, lane = tid & 31;
    const int g = lane >> 2, t2 = (lane & 3) * 2;
    const int mr = (warp >> 2) * 64, nc = (warp & 3) * 16;
    float acc[4][2][4];
#pragma unroll
    for (int mt = 0; mt < 4; mt++)
#pragma unroll
        for (int nt = 0; nt < 2; nt++)
#pragma unroll
            for (int q = 0; q < 4; q++) acc[mt][nt][q] = 0.f;

#pragma unroll
    for (int kt = 0; kt < 12; kt++) {                 // pass 1: SP @ W6a^T
        const int kk = kt * 16;
        uint32_t a[4][4];
#pragma unroll
        for (int mt = 0; mt < 4; mt++) {
            int rb = mr + mt * 16 + g;
            a[mt][0] = ld2(As, rb * AK + kk + t2);
            a[mt][1] = ld2(As, (rb + 8) * AK + kk + t2);
            a[mt][2] = ld2(As, rb * AK + kk + 8 + t2);
            a[mt][3] = ld2(As, (rb + 8) * AK + kk + 8 + t2);
        }
        uint32_t bb[2][2];
#pragma unroll
        for (int nt = 0; nt < 2; nt++) {
            int n = nc + nt * 8 + g;
            bb[nt][0] = ld2(Bs, n * BK3 + kk + t2);
            bb[nt][1] = ld2(Bs, n * BK3 + kk + 8 + t2);
        }
#pragma unroll
        for (int mt = 0; mt < 4; mt++)
#pragma unroll
            for (int nt = 0; nt < 2; nt++)
                mma16(acc[mt][nt], a[mt][0], a[mt][1], a[mt][2], a[mt][3], bb[nt][0], bb[nt][1]);
    }
    __syncthreads();

    // restage A = prod rows (transpose from channel-major scratch)
#pragma unroll
    for (int it = 0; it < 8; it++) {
        int idx = tid + it * 256;
        int e0 = idx * 4;
        int m0 = e0 & 127, c = e0 >> 7;
        float4 v = *(const float4*)(g_prod + ((size_t)(b * 64 + c)) * 4096 + rig + m0);
        float e[4] = {v.x, v.y, v.z, v.w};
#pragma unroll
        for (int q = 0; q < 4; q++) {
            unsigned short h, l; splitb(e[q], h, l);
            int m = m0 + q;
            As[m * AK + c] = h; As[m * AK + 64 + c] = h; As[m * AK + 128 + c] = l;
        }
    }
    __syncthreads();

#pragma unroll
    for (int kt = 0; kt < 12; kt++) {                 // pass 2: + prod @ W6b^T
        const int kk = kt * 16;
        uint32_t a[4][4];
#pragma unroll
        for (int mt = 0; mt < 4; mt++) {
            int rb = mr + mt * 16 + g;
            a[mt][0] = ld2(As, rb * AK + kk + t2);
            a[mt][1] = ld2(As, (rb + 8) * AK + kk + t2);
            a[mt][2] = ld2(As, rb * AK + kk + 8 + t2);
            a[mt][3] = ld2(As, (rb + 8) * AK + kk + 8 + t2);
        }
        uint32_t bb[2][2];
#pragma unroll
        for (int nt = 0; nt < 2; nt++) {
            int n = nc + nt * 8 + g;
            bb[nt][0] = ld2(Bs, n * BK3 + 200 + kk + t2);
            bb[nt][1] = ld2(Bs, n * BK3 + 200 + kk + 8 + t2);
        }
#pragma unroll
        for (int mt = 0; mt < 4; mt++)
#pragma unroll
            for (int nt = 0; nt < 2; nt++)
                mma16(acc[mt][nt], a[mt][0], a[mt][1], a[mt][2], a[mt][3], bb[nt][0], bb[nt][1]);
    }
    __syncthreads();

    float* Ds = (float*)smraw;                        // [128 rows][68]
#pragma unroll
    for (int mt = 0; mt < 4; mt++)
#pragma unroll
        for (int nt = 0; nt < 2; nt++) {
            int row = mr + mt * 16 + g;
            int col = nc + nt * 8 + t2;
            Ds[row * 68 + col]           = fmaxf(acc[mt][nt][0], 0.f);
            Ds[row * 68 + col + 1]       = fmaxf(acc[mt][nt][1], 0.f);
            Ds[(row + 8) * 68 + col]     = fmaxf(acc[mt][nt][2], 0.f);
            Ds[(row + 8) * 68 + col + 1] = fmaxf(acc[mt][nt][3], 0.f);
        }
    __syncthreads();
    float* ob = out + (size_t)row0 * 64;
#pragma unroll
    for (int it = 0; it < 32; it++) {
        int idx = tid + it * 256;
        ob[idx] = Ds[(idx >> 6) * 68 + (idx & 63)];
    }
}

// ---------------------------------------------------------------------------
extern "C" void kernel_launch(void* const* d_in, const int* in_sizes, int n_in,
                              void* d_out, int out_size) {
    const float* SP = nullptr; const float* W4 = nullptr;
    const float* W5 = nullptr; const float* W6 = nullptr;
    for (int i = 0; i < n_in; i++) {
        int sz = in_sizes[i];
        if (sz == 67108864)      SP = (const float*)d_in[i];
        else if (sz == 8192)     W6 = (const float*)d_in[i];
        else if (sz == 4096)     { if (!W4) W4 = (const float*)d_in[i]; else W5 = (const float*)d_in[i]; }
    }
    float* out = (float*)d_out;

    const int smem12 = (128 * AK + 128 * AK) * 2;          // 102400
    const int smem3  = (128 * AK) * 2 + (64 * BK3) * 2;    // 103424
    cudaFuncSetAttribute(k1, cudaFuncAttributeMaxDynamicSharedMemorySize, smem12);
    cudaFuncSetAttribute(k2, cudaFuncAttributeMaxDynamicSharedMemorySize, smem12);
    cudaFuncSetAttribute(k3, cudaFuncAttributeMaxDynamicSharedMemorySize, smem3);

    k1<<<8192, 256, smem12>>>(SP, W4, W5);
    k2<<<8192, 256, smem12>>>();
    k3<<<8192, 256, smem3>>>(SP, W6, out);
}

// round 5
// speedup vs baseline: 2.2036x; 1.5220x over previous
#include <cuda_runtime.h>
#include <cuda_bf16.h>
#include <cstdint>
#include <cstddef>

// 256 graphs x 64 nodes; E=1048576 rows (r = b*4096 + i*64 + j); C=64.
// K1: X=SP@W4^T/64, Y=SP@W5^T/64 -> packed (hi|lo) bf16 scratch [b*64+c][4096]
// K2: per (b, channel-pair): prod_c = X_c @ Y_c -> packed scratch
// K3: out = relu(SP@W6a^T + prod@W6b^T)
// mma.sync m16n8k16 bf16, 3-term split: A=[hi|hi|lo], B=[hi|lo|hi] along K.
// Fragments via ldmatrix (.trans for transposed-layout operands).

__device__ unsigned int g_Xt[67108864];
__device__ unsigned int g_Yt[67108864];
__device__ unsigned int g_prod[67108864];

#define AK   200   // [m][k] tiles: 192 data + 8 pad (shorts)
#define BK3  408   // K3 W6 tile: two 200-wide K-segments + pad
#define K2BS 72    // K2 B tile [k][j]: 64 + 8 pad
#define A2S  136   // K3 pass2 A tile [c][m]: 128 + 8 pad

__device__ __forceinline__ uint32_t smem_u32(const void* p) {
    uint32_t a; asm("{ .reg .u64 t; cvta.to.shared.u64 t, %1; cvt.u32.u64 %0, t; }" : "=r"(a) : "l"(p));
    return a;
}
__device__ __forceinline__ void splitb(float v, unsigned short& h, unsigned short& l) {
    __nv_bfloat16 hb = __float2bfloat16_rn(v);
    float r = v - __bfloat162float(hb);
    __nv_bfloat16 lb = __float2bfloat16_rn(r);
    h = reinterpret_cast<unsigned short&>(hb);
    l = reinterpret_cast<unsigned short&>(lb);
}
__device__ __forceinline__ uint32_t splitpack(float v) {
    unsigned short h, l; splitb(v, h, l);
    return (uint32_t)h | ((uint32_t)l << 16);
}
__device__ __forceinline__ uint32_t prmt(uint32_t a, uint32_t b, uint32_t s) {
    uint32_t d; asm("prmt.b32 %0,%1,%2,%3;" : "=r"(d) : "r"(a), "r"(b), "r"(s)); return d;
}
__device__ __forceinline__ void ldsm4(uint32_t* r, uint32_t a) {
    asm volatile("ldmatrix.sync.aligned.m8n8.x4.shared.b16 {%0,%1,%2,%3}, [%4];"
                 : "=r"(r[0]), "=r"(r[1]), "=r"(r[2]), "=r"(r[3]) : "r"(a));
}
__device__ __forceinline__ void ldsm4t(uint32_t* r, uint32_t a) {
    asm volatile("ldmatrix.sync.aligned.m8n8.x4.trans.shared.b16 {%0,%1,%2,%3}, [%4];"
                 : "=r"(r[0]), "=r"(r[1]), "=r"(r[2]), "=r"(r[3]) : "r"(a));
}
__device__ __forceinline__ void mma16(float* c, uint32_t a0, uint32_t a1, uint32_t a2, uint32_t a3,
                                      uint32_t b0, uint32_t b1) {
    asm volatile("mma.sync.aligned.m16n8k16.row.col.f32.bf16.bf16.f32 "
                 "{%0,%1,%2,%3},{%4,%5,%6,%7},{%8,%9},{%0,%1,%2,%3};"
                 : "+f"(c[0]), "+f"(c[1]), "+f"(c[2]), "+f"(c[3])
                 : "r"(a0), "r"(a1), "r"(a2), "r"(a3), "r"(b0), "r"(b1));
}

// ===================== K1 =====================
__global__ __launch_bounds__(256) void k1(const float* __restrict__ SP,
                                          const float* __restrict__ W4,
                                          const float* __restrict__ W5) {
    extern __shared__ char smraw[];
    unsigned short* As = (unsigned short*)smraw;      // [128][AK]
    unsigned short* Bs = As + 128 * AK;               // [128][AK]
    const int tid = threadIdx.x;
    const int row0 = blockIdx.x * 128;
    const int b = row0 >> 12, rig = row0 & 4095;

    const float4* SPg = (const float4*)(SP + (size_t)row0 * 64);
#pragma unroll
    for (int it = 0; it < 8; it++) {
        int idx = tid + it * 256;
        float4 v = SPg[idx];
        int r = idx >> 4, k0 = (idx & 15) * 4;
        unsigned short h0,l0,h1,l1,h2,l2,h3,l3;
        splitb(v.x,h0,l0); splitb(v.y,h1,l1); splitb(v.z,h2,l2); splitb(v.w,h3,l3);
        uint2 hh = make_uint2((uint32_t)h0 | ((uint32_t)h1<<16), (uint32_t)h2 | ((uint32_t)h3<<16));
        uint2 ll = make_uint2((uint32_t)l0 | ((uint32_t)l1<<16), (uint32_t)l2 | ((uint32_t)l3<<16));
        *(uint2*)&As[r*AK + k0]       = hh;
        *(uint2*)&As[r*AK + 64 + k0]  = hh;
        *(uint2*)&As[r*AK + 128 + k0] = ll;
    }
#pragma unroll
    for (int it = 0; it < 8; it++) {
        int idx = tid + it * 256;
        int n = idx >> 4, k0 = (idx & 15) * 4;
        float4 v = (n < 64) ? ((const float4*)W4)[idx] : ((const float4*)W5)[idx - 1024];
        unsigned short h0,l0,h1,l1,h2,l2,h3,l3;
        splitb(v.x,h0,l0); splitb(v.y,h1,l1); splitb(v.z,h2,l2); splitb(v.w,h3,l3);
        uint2 hh = make_uint2((uint32_t)h0 | ((uint32_t)h1<<16), (uint32_t)h2 | ((uint32_t)h3<<16));
        uint2 ll = make_uint2((uint32_t)l0 | ((uint32_t)l1<<16), (uint32_t)l2 | ((uint32_t)l3<<16));
        *(uint2*)&Bs[n*AK + k0]       = hh;
        *(uint2*)&Bs[n*AK + 64 + k0]  = ll;
        *(uint2*)&Bs[n*AK + 128 + k0] = hh;
    }
    __syncthreads();

    const int warp = tid >> 5, lane = tid & 31;
    const int lrow = lane & 15, lcol8 = (lane >> 4) * 8;
    const int mr = (warp >> 2) * 64, nc = (warp & 3) * 32;
    const uint32_t as_u = smem_u32(As), bs_u = smem_u32(Bs);
    float acc[4][4][4] = {};

#pragma unroll
    for (int kt = 0; kt < 12; kt++) {
        const int kk = kt * 16;
        uint32_t a[4][4], bf[2][4];
#pragma unroll
        for (int mt = 0; mt < 4; mt++)
            ldsm4(a[mt], as_u + (uint32_t)(((mr + mt*16 + lrow) * AK) + kk + lcol8) * 2);
#pragma unroll
        for (int nb = 0; nb < 2; nb++)
            ldsm4(bf[nb], bs_u + (uint32_t)(((nc + nb*16 + lrow) * AK) + kk + lcol8) * 2);
        // x4 on [n][k]: {r0,r1,r2,r3} = {b0@n0, b0@n0+8, b1@n0, b1@n0+8}
#pragma unroll
        for (int mt = 0; mt < 4; mt++)
#pragma unroll
            for (int nt = 0; nt < 4; nt++)
                mma16(acc[mt][nt], a[mt][0], a[mt][1], a[mt][2], a[mt][3],
                      bf[nt>>1][nt&1], bf[nt>>1][2 + (nt&1)]);
    }
    __syncthreads();

    uint32_t* Ds = (uint32_t*)smraw;                  // [128 c][132 m] packed
    const int g = lane >> 2, t2 = (lane & 3) * 2;
#pragma unroll
    for (int mt = 0; mt < 4; mt++)
#pragma unroll
        for (int nt = 0; nt < 4; nt++) {
            int row = mr + mt*16 + g;
            int col = nc + nt*8 + t2;
            Ds[col*132 + row]         = splitpack(acc[mt][nt][0] * 0.015625f);
            Ds[(col+1)*132 + row]     = splitpack(acc[mt][nt][1] * 0.015625f);
            Ds[col*132 + row + 8]     = splitpack(acc[mt][nt][2] * 0.015625f);
            Ds[(col+1)*132 + row + 8] = splitpack(acc[mt][nt][3] * 0.015625f);
        }
    __syncthreads();
#pragma unroll
    for (int it = 0; it < 16; it++) {
        int idx = tid + it * 256;
        int c = idx >> 5, m4 = (idx & 31) * 4;
        uint4 v = *(const uint4*)&Ds[c*132 + m4];
        if (c < 64) *(uint4*)&g_Xt[(size_t)(b*64 + c)*4096 + rig + m4] = v;
        else        *(uint4*)&g_Yt[(size_t)(b*64 + c - 64)*4096 + rig + m4] = v;
    }
}

// ===================== K2 =====================
__global__ __launch_bounds__(256) void k2() {
    extern __shared__ char smraw[];
    unsigned short* As = (unsigned short*)smraw;      // [128][AK]  [X_c1; X_c2]
    unsigned short* Bs = As + 128 * AK;               // 2 x [192][K2BS]  Y natural [k][j]
    const int tid = threadIdx.x;
    const int b = blockIdx.x >> 5, c1 = (blockIdx.x & 31) * 2;
    const size_t base = (size_t)(b*64 + c1) * 4096;

    const uint4* Xg = (const uint4*)(g_Xt + base);
#pragma unroll
    for (int it = 0; it < 8; it++) {
        int idx = tid + it * 256;
        uint4 p = Xg[idx];
        int e0 = idx * 4;
        int k0 = e0 & 63, m = (e0 >> 12) * 64 + ((e0 >> 6) & 63);
        uint2 hh = make_uint2(prmt(p.x, p.y, 0x5410), prmt(p.z, p.w, 0x5410));
        uint2 ll = make_uint2(prmt(p.x, p.y, 0x7632), prmt(p.z, p.w, 0x7632));
        *(uint2*)&As[m*AK + k0]       = hh;
        *(uint2*)&As[m*AK + 64 + k0]  = hh;
        *(uint2*)&As[m*AK + 128 + k0] = ll;
    }
    const uint4* Yg = (const uint4*)(g_Yt + base);
#pragma unroll
    for (int it = 0; it < 8; it++) {
        int idx = tid + it * 256;
        uint4 p = Yg[idx];
        int e0 = idx * 4;
        int j0 = e0 & 63, k = (e0 >> 6) & 63, cid = e0 >> 12;
        unsigned short* Bc = Bs + cid * 192 * K2BS;
        uint2 hh = make_uint2(prmt(p.x, p.y, 0x5410), prmt(p.z, p.w, 0x5410));
        uint2 ll = make_uint2(prmt(p.x, p.y, 0x7632), prmt(p.z, p.w, 0x7632));
        *(uint2*)&Bc[k*K2BS + j0]        = hh;
        *(uint2*)&Bc[(64+k)*K2BS + j0]   = ll;
        *(uint2*)&Bc[(128+k)*K2BS + j0]  = hh;
    }
    __syncthreads();

    const int warp = tid >> 5, lane = tid & 31;
    const int lrow = lane & 15, lcol8 = (lane >> 4) * 8;
    const int hf = warp >> 2;
    const int mr = hf * 64, n0 = (warp & 3) * 16;
    const uint32_t as_u = smem_u32(As);
    const uint32_t bs_u = smem_u32(Bs + hf * 192 * K2BS);
    // x4.trans on [k][j]: rows kk + (lane&7) + 8*((lane>>3)&1), col n0 + 8*(lane>>4)
    const int brow = (lane & 7) + 8 * ((lane >> 3) & 1);
    const int bcol = n0 + 8 * (lane >> 4);
    float acc[4][2][4] = {};

#pragma unroll
    for (int kt = 0; kt < 12; kt++) {
        const int kk = kt * 16;
        uint32_t a[4][4], bf[4];
#pragma unroll
        for (int mt = 0; mt < 4; mt++)
            ldsm4(a[mt], as_u + (uint32_t)(((mr + mt*16 + lrow) * AK) + kk + lcol8) * 2);
        ldsm4t(bf, bs_u + (uint32_t)(((kk + brow) * K2BS) + bcol) * 2);
        // {r0,r1,r2,r3} = {b0@n0, b1@n0, b0@n0+8, b1@n0+8}
#pragma unroll
        for (int mt = 0; mt < 4; mt++) {
            mma16(acc[mt][0], a[mt][0], a[mt][1], a[mt][2], a[mt][3], bf[0], bf[1]);
            mma16(acc[mt][1], a[mt][0], a[mt][1], a[mt][2], a[mt][3], bf[2], bf[3]);
        }
    }
    __syncthreads();

    uint32_t* Ds = (uint32_t*)smraw;                  // [128][68] packed
    const int g = lane >> 2, t2 = (lane & 3) * 2;
#pragma unroll
    for (int mt = 0; mt < 4; mt++)
#pragma unroll
        for (int nt = 0; nt < 2; nt++) {
            int row = mr + mt*16 + g;
            int jl = (warp & 3) * 16 + nt*8 + t2;
            Ds[row*68 + jl]         = splitpack(acc[mt][nt][0]);
            Ds[row*68 + jl + 1]     = splitpack(acc[mt][nt][1]);
            Ds[(row+8)*68 + jl]     = splitpack(acc[mt][nt][2]);
            Ds[(row+8)*68 + jl + 1] = splitpack(acc[mt][nt][3]);
        }
    __syncthreads();
#pragma unroll
    for (int it = 0; it < 8; it++) {
        int idx = tid + it * 256;
        int row = idx >> 4, j4 = (idx & 15) * 4;
        uint4 v = *(const uint4*)&Ds[row*68 + j4];
        *(uint4*)&g_prod[base + (size_t)row*64 + j4] = v;
    }
}

// ===================== K3 =====================
__global__ __launch_bounds__(256) void k3(const float* __restrict__ SP,
                                          const float* __restrict__ W6,
                                          float* __restrict__ out) {
    extern __shared__ char smraw[];
    unsigned short* As = (unsigned short*)smraw;               // union: [128][AK] | [192][A2S]
    unsigned short* Bs = (unsigned short*)(smraw + 52224);     // [64][BK3]
    const int tid = threadIdx.x;
    const int row0 = blockIdx.x * 128;
    const int b = row0 >> 12, rig = row0 & 4095;

    const float4* SPg = (const float4*)(SP + (size_t)row0 * 64);
#pragma unroll
    for (int it = 0; it < 8; it++) {
        int idx = tid + it * 256;
        float4 v = SPg[idx];
        int r = idx >> 4, k0 = (idx & 15) * 4;
        unsigned short h0,l0,h1,l1,h2,l2,h3,l3;
        splitb(v.x,h0,l0); splitb(v.y,h1,l1); splitb(v.z,h2,l2); splitb(v.w,h3,l3);
        uint2 hh = make_uint2((uint32_t)h0 | ((uint32_t)h1<<16), (uint32_t)h2 | ((uint32_t)h3<<16));
        uint2 ll = make_uint2((uint32_t)l0 | ((uint32_t)l1<<16), (uint32_t)l2 | ((uint32_t)l3<<16));
        *(uint2*)&As[r*AK + k0]       = hh;
        *(uint2*)&As[r*AK + 64 + k0]  = hh;
        *(uint2*)&As[r*AK + 128 + k0] = ll;
    }
#pragma unroll
    for (int it = 0; it < 8; it++) {
        int idx = tid + it * 256;
        int o = idx >> 5, m0 = (idx & 31) * 4;
        float4 v = ((const float4*)W6)[idx];
        unsigned short h0,l0,h1,l1,h2,l2,h3,l3;
        splitb(v.x,h0,l0); splitb(v.y,h1,l1); splitb(v.z,h2,l2); splitb(v.w,h3,l3);
        uint2 hh = make_uint2((uint32_t)h0 | ((uint32_t)h1<<16), (uint32_t)h2 | ((uint32_t)h3<<16));
        uint2 ll = make_uint2((uint32_t)l0 | ((uint32_t)l1<<16), (uint32_t)l2 | ((uint32_t)l3<<16));
        int s = (m0 < 64) ? 0 : 200;
        int k0 = m0 & 63;
        *(uint2*)&Bs[o*BK3 + s + k0]       = hh;
        *(uint2*)&Bs[o*BK3 + s + 64 + k0]  = ll;
        *(uint2*)&Bs[o*BK3 + s + 128 + k0] = hh;
    }
    __syncthreads();

    const int warp = tid >> 5, lane = tid & 31;
    const int lrow = lane & 15, lcol8 = (lane >> 4) * 8;
    const int mr = (warp >> 2) * 64, nc = (warp & 3) * 16;
    const uint32_t as_u = smem_u32(As), bs_u = smem_u32(Bs);
    float acc[4][2][4] = {};

#pragma unroll
    for (int kt = 0; kt < 12; kt++) {                 // pass 1: SP @ W6a^T
        const int kk = kt * 16;
        uint32_t a[4][4], bf[4];
#pragma unroll
        for (int mt = 0; mt < 4; mt++)
            ldsm4(a[mt], as_u + (uint32_t)(((mr + mt*16 + lrow) * AK) + kk + lcol8) * 2);
        ldsm4(bf, bs_u + (uint32_t)(((nc + lrow) * BK3) + kk + lcol8) * 2);
        // {b0@nc, b0@nc+8, b1@nc, b1@nc+8}
#pragma unroll
        for (int mt = 0; mt < 4; mt++) {
            mma16(acc[mt][0], a[mt][0], a[mt][1], a[mt][2], a[mt][3], bf[0], bf[2]);
            mma16(acc[mt][1], a[mt][0], a[mt][1], a[mt][2], a[mt][3], bf[1], bf[3]);
        }
    }
    __syncthreads();

    // restage A = prod, natural [c][m] layout (pre-split packed scratch)
#pragma unroll
    for (int it = 0; it < 8; it++) {
        int idx = tid + it * 256;
        int e0 = idx * 4;
        int m0 = e0 & 127, c = e0 >> 7;
        uint4 p = *(const uint4*)&g_prod[(size_t)(b*64 + c)*4096 + rig + m0];
        uint2 hh = make_uint2(prmt(p.x, p.y, 0x5410), prmt(p.z, p.w, 0x5410));
        uint2 ll = make_uint2(prmt(p.x, p.y, 0x7632), prmt(p.z, p.w, 0x7632));
        *(uint2*)&As[c*A2S + m0]        = hh;
        *(uint2*)&As[(64+c)*A2S + m0]   = hh;
        *(uint2*)&As[(128+c)*A2S + m0]  = ll;
    }
    __syncthreads();

    // pass 2: + prod @ W6b^T.  A via ldmatrix.trans from [k=c][m] storage.
    const int arow = (lane & 7) + 8 * (lane >> 4);
    const int acol8 = 8 * ((lane >> 3) & 1);
#pragma unroll
    for (int kt = 0; kt < 12; kt++) {
        const int kk = kt * 16;
        uint32_t a[4][4], bf[4];
#pragma unroll
        for (int mt = 0; mt < 4; mt++)
            ldsm4t(a[mt], as_u + (uint32_t)(((kk + arow) * A2S) + mr + mt*16 + acol8) * 2);
        ldsm4(bf, bs_u + (uint32_t)(((nc + lrow) * BK3) + 200 + kk + lcol8) * 2);
#pragma unroll
        for (int mt = 0; mt < 4; mt++) {
            mma16(acc[mt][0], a[mt][0], a[mt][1], a[mt][2], a[mt][3], bf[0], bf[2]);
            mma16(acc[mt][1], a[mt][0], a[mt][1], a[mt][2], a[mt][3], bf[1], bf[3]);
        }
    }
    __syncthreads();

    float* Ds = (float*)smraw;                        // [128][68]
    const int g = lane >> 2, t2 = (lane & 3) * 2;
#pragma unroll
    for (int mt = 0; mt < 4; mt++)
#pragma unroll
        for (int nt = 0; nt < 2; nt++) {
            int row = mr + mt*16 + g;
            int col = nc + nt*8 + t2;
            Ds[row*68 + col]         = fmaxf(acc[mt][nt][0], 0.f);
            Ds[row*68 + col + 1]     = fmaxf(acc[mt][nt][1], 0.f);
            Ds[(row+8)*68 + col]     = fmaxf(acc[mt][nt][2], 0.f);
            Ds[(row+8)*68 + col + 1] = fmaxf(acc[mt][nt][3], 0.f);
        }
    __syncthreads();
    float* ob = out + (size_t)row0 * 64;
#pragma unroll
    for (int it = 0; it < 8; it++) {
        int idx = tid + it * 256;
        int m = idx >> 4, o4 = (idx & 15) * 4;
        *(float4*)&ob[m*64 + o4] = *(const float4*)&Ds[m*68 + o4];
    }
}

// ---------------------------------------------------------------------------
extern "C" void kernel_launch(void* const* d_in, const int* in_sizes, int n_in,
                              void* d_out, int out_size) {
    const float* SP = nullptr; const float* W4 = nullptr;
    const float* W5 = nullptr; const float* W6 = nullptr;
    for (int i = 0; i < n_in; i++) {
        int sz = in_sizes[i];
        if (sz == 67108864)      SP = (const float*)d_in[i];
        else if (sz == 8192)     W6 = (const float*)d_in[i];
        else if (sz == 4096)     { if (!W4) W4 = (const float*)d_in[i]; else W5 = (const float*)d_in[i]; }
    }
    float* out = (float*)d_out;

    const int smem1 = 2 * (128 * AK) * 2;                       // 102400
    const int smem2 = (128 * AK) * 2 + 2 * (192 * K2BS) * 2;    // 106496
    const int smem3 = 52224 + (64 * BK3) * 2;                   // 104448
    cudaFuncSetAttribute(k1, cudaFuncAttributeMaxDynamicSharedMemorySize, smem1);
    cudaFuncSetAttribute(k2, cudaFuncAttributeMaxDynamicSharedMemorySize, smem2);
    cudaFuncSetAttribute(k3, cudaFuncAttributeMaxDynamicSharedMemorySize, smem3);

    k1<<<8192, 256, smem1>>>(SP, W4, W5);
    k2<<<8192, 256, smem2>>>();
    k3<<<8192, 256, smem3>>>(SP, W6, out);
}

// round 7
// speedup vs baseline: 2.7481x; 1.2471x over previous
#include <cuda_runtime.h>
#include <cuda_bf16.h>
#include <cstdint>
#include <cstddef>

// 256 graphs x 64 nodes; E=1048576 rows (r = b*4096 + i*64 + j); C=64.
// K1: X=SP@W4^T/64, Y=SP@W5^T/64 -> packed (hi|lo) bf16 scratch [b*64+c][4096]
// K2: per (b, channel-pair): prod_c = X_c @ Y_c -> packed scratch
// K3: out = relu(SP@W6a^T + prod@W6b^T)
// mma.sync m16n8k16 bf16. 3-term split via REGISTER REUSE of hi/lo planes:
//   acc += a_hi*b_hi + a_hi*b_lo + a_lo*b_hi   (~1e-5 rel; same math as before)

__device__ unsigned int g_Xt[67108864];
__device__ unsigned int g_Yt[67108864];
__device__ unsigned int g_prod[67108864];

#define AK2  136   // [m][k] tiles: 64 hi + 64 lo + 8 pad (shorts)
#define K2BS 72    // K2 B tile [k][j]: 64 + 8 pad (128 rows: 64 hi + 64 lo)
#define BK3  280   // K3 W6 tile row: (64hi+64lo) pass1 | at 136: (64hi+64lo) pass2, +pad

__device__ __forceinline__ uint32_t smem_u32(const void* p) {
    uint32_t a; asm("{ .reg .u64 t; cvta.to.shared.u64 t, %1; cvt.u32.u64 %0, t; }" : "=r"(a) : "l"(p));
    return a;
}
__device__ __forceinline__ void splitb(float v, unsigned short& h, unsigned short& l) {
    __nv_bfloat16 hb = __float2bfloat16_rn(v);
    float r = v - __bfloat162float(hb);
    __nv_bfloat16 lb = __float2bfloat16_rn(r);
    h = reinterpret_cast<unsigned short&>(hb);
    l = reinterpret_cast<unsigned short&>(lb);
}
__device__ __forceinline__ uint32_t splitpack(float v) {
    unsigned short h, l; splitb(v, h, l);
    return (uint32_t)h | ((uint32_t)l << 16);
}
__device__ __forceinline__ uint32_t prmt(uint32_t a, uint32_t b, uint32_t s) {
    uint32_t d; asm("prmt.b32 %0,%1,%2,%3;" : "=r"(d) : "r"(a), "r"(b), "r"(s)); return d;
}
__device__ __forceinline__ void ldsm4(uint32_t* r, uint32_t a) {
    asm volatile("ldmatrix.sync.aligned.m8n8.x4.shared.b16 {%0,%1,%2,%3}, [%4];"
                 : "=r"(r[0]), "=r"(r[1]), "=r"(r[2]), "=r"(r[3]) : "r"(a));
}
__device__ __forceinline__ void ldsm4t(uint32_t* r, uint32_t a) {
    asm volatile("ldmatrix.sync.aligned.m8n8.x4.trans.shared.b16 {%0,%1,%2,%3}, [%4];"
                 : "=r"(r[0]), "=r"(r[1]), "=r"(r[2]), "=r"(r[3]) : "r"(a));
}
__device__ __forceinline__ void mma16(float* c, const uint32_t* a, uint32_t b0, uint32_t b1) {
    asm volatile("mma.sync.aligned.m16n8k16.row.col.f32.bf16.bf16.f32 "
                 "{%0,%1,%2,%3},{%4,%5,%6,%7},{%8,%9},{%0,%1,%2,%3};"
                 : "+f"(c[0]), "+f"(c[1]), "+f"(c[2]), "+f"(c[3])
                 : "r"(a[0]), "r"(a[1]), "r"(a[2]), "r"(a[3]), "r"(b0), "r"(b1));
}

// ===================== K1 =====================
__global__ __launch_bounds__(256, 2) void k1(const float* __restrict__ SP,
                                             const float* __restrict__ W4,
                                             const float* __restrict__ W5) {
    extern __shared__ char smraw[];
    unsigned short* As = (unsigned short*)smraw;      // [128][AK2]  hi k0-63, lo 64-127
    unsigned short* Bs = As + 128 * AK2;              // [128][AK2]
    const int tid = threadIdx.x;
    const int row0 = blockIdx.x * 128;
    const int b = row0 >> 12, rig = row0 & 4095;

    const float4* SPg = (const float4*)(SP + (size_t)row0 * 64);
#pragma unroll
    for (int it = 0; it < 8; it++) {
        int idx = tid + it * 256;
        float4 v = SPg[idx];
        int r = idx >> 4, k0 = (idx & 15) * 4;
        unsigned short h0,l0,h1,l1,h2,l2,h3,l3;
        splitb(v.x,h0,l0); splitb(v.y,h1,l1); splitb(v.z,h2,l2); splitb(v.w,h3,l3);
        *(uint2*)&As[r*AK2 + k0]      = make_uint2((uint32_t)h0|((uint32_t)h1<<16), (uint32_t)h2|((uint32_t)h3<<16));
        *(uint2*)&As[r*AK2 + 64 + k0] = make_uint2((uint32_t)l0|((uint32_t)l1<<16), (uint32_t)l2|((uint32_t)l3<<16));
    }
#pragma unroll
    for (int it = 0; it < 8; it++) {
        int idx = tid + it * 256;
        int n = idx >> 4, k0 = (idx & 15) * 4;
        float4 v = (n < 64) ? ((const float4*)W4)[idx] : ((const float4*)W5)[idx - 1024];
        unsigned short h0,l0,h1,l1,h2,l2,h3,l3;
        splitb(v.x,h0,l0); splitb(v.y,h1,l1); splitb(v.z,h2,l2); splitb(v.w,h3,l3);
        *(uint2*)&Bs[n*AK2 + k0]      = make_uint2((uint32_t)h0|((uint32_t)h1<<16), (uint32_t)h2|((uint32_t)h3<<16));
        *(uint2*)&Bs[n*AK2 + 64 + k0] = make_uint2((uint32_t)l0|((uint32_t)l1<<16), (uint32_t)l2|((uint32_t)l3<<16));
    }
    __syncthreads();

    const int warp = tid >> 5, lane = tid & 31;
    const int lrow = lane & 15, lcol8 = (lane >> 4) * 8;
    const int mr = (warp >> 2) * 64, nc = (warp & 3) * 32;
    const uint32_t as_u = smem_u32(As), bs_u = smem_u32(Bs);
    float acc[4][4][4] = {};

#pragma unroll
    for (int kt = 0; kt < 4; kt++) {
        const int kk = kt * 16;
        uint32_t ah[4][4], al[4][4], bh[2][4], bl[2][4];
#pragma unroll
        for (int mt = 0; mt < 4; mt++) {
            uint32_t base = as_u + (uint32_t)(((mr + mt*16 + lrow) * AK2) + kk + lcol8) * 2;
            ldsm4(ah[mt], base);
            ldsm4(al[mt], base + 128);        // +64 shorts
        }
#pragma unroll
        for (int nb = 0; nb < 2; nb++) {
            uint32_t base = bs_u + (uint32_t)(((nc + nb*16 + lrow) * AK2) + kk + lcol8) * 2;
            ldsm4(bh[nb], base);
            ldsm4(bl[nb], base + 128);
        }
        // x4 on [n][k]: {r0,r1,r2,r3} = {b0@n0, b0@n0+8, b1@n0, b1@n0+8}
#pragma unroll
        for (int mt = 0; mt < 4; mt++)
#pragma unroll
            for (int nt = 0; nt < 4; nt++) {
                uint32_t b0h = bh[nt>>1][nt&1], b1h = bh[nt>>1][2+(nt&1)];
                mma16(acc[mt][nt], ah[mt], b0h, b1h);
                mma16(acc[mt][nt], ah[mt], bl[nt>>1][nt&1], bl[nt>>1][2+(nt&1)]);
                mma16(acc[mt][nt], al[mt], b0h, b1h);
            }
    }
    __syncthreads();

    uint32_t* Ds = (uint32_t*)smraw;                  // [128 c][132 m] packed
    const int g = lane >> 2, t2 = (lane & 3) * 2;
#pragma unroll
    for (int mt = 0; mt < 4; mt++)
#pragma unroll
        for (int nt = 0; nt < 4; nt++) {
            int row = mr + mt*16 + g;
            int col = nc + nt*8 + t2;
            Ds[col*132 + row]         = splitpack(acc[mt][nt][0] * 0.015625f);
            Ds[(col+1)*132 + row]     = splitpack(acc[mt][nt][1] * 0.015625f);
            Ds[col*132 + row + 8]     = splitpack(acc[mt][nt][2] * 0.015625f);
            Ds[(col+1)*132 + row + 8] = splitpack(acc[mt][nt][3] * 0.015625f);
        }
    __syncthreads();
#pragma unroll
    for (int it = 0; it < 16; it++) {
        int idx = tid + it * 256;
        int c = idx >> 5, m4 = (idx & 31) * 4;
        uint4 v = *(const uint4*)&Ds[c*132 + m4];
        if (c < 64) *(uint4*)&g_Xt[(size_t)(b*64 + c)*4096 + rig + m4] = v;
        else        *(uint4*)&g_Yt[(size_t)(b*64 + c - 64)*4096 + rig + m4] = v;
    }
}

// ===================== K2 =====================
__global__ __launch_bounds__(256, 2) void k2() {
    extern __shared__ char smraw[];
    unsigned short* As = (unsigned short*)smraw;      // [128][AK2]  [X_c1; X_c2]
    unsigned short* Bs = As + 128 * AK2;              // 2 x [128][K2BS]: rows 0-63 hi(k), 64-127 lo(k)
    const int tid = threadIdx.x;
    const int b = blockIdx.x >> 5, c1 = (blockIdx.x & 31) * 2;
    const size_t base = (size_t)(b*64 + c1) * 4096;

    const uint4* Xg = (const uint4*)(g_Xt + base);
#pragma unroll
    for (int it = 0; it < 8; it++) {
        int idx = tid + it * 256;
        uint4 p = Xg[idx];
        int e0 = idx * 4;
        int k0 = e0 & 63, m = (e0 >> 12) * 64 + ((e0 >> 6) & 63);
        *(uint2*)&As[m*AK2 + k0]      = make_uint2(prmt(p.x,p.y,0x5410), prmt(p.z,p.w,0x5410));
        *(uint2*)&As[m*AK2 + 64 + k0] = make_uint2(prmt(p.x,p.y,0x7632), prmt(p.z,p.w,0x7632));
    }
    const uint4* Yg = (const uint4*)(g_Yt + base);
#pragma unroll
    for (int it = 0; it < 8; it++) {
        int idx = tid + it * 256;
        uint4 p = Yg[idx];
        int e0 = idx * 4;
        int j0 = e0 & 63, k = (e0 >> 6) & 63, cid = e0 >> 12;
        unsigned short* Bc = Bs + cid * 128 * K2BS;
        *(uint2*)&Bc[k*K2BS + j0]        = make_uint2(prmt(p.x,p.y,0x5410), prmt(p.z,p.w,0x5410));
        *(uint2*)&Bc[(64+k)*K2BS + j0]   = make_uint2(prmt(p.x,p.y,0x7632), prmt(p.z,p.w,0x7632));
    }
    __syncthreads();

    const int warp = tid >> 5, lane = tid & 31;
    const int lrow = lane & 15, lcol8 = (lane >> 4) * 8;
    const int hf = warp >> 2;
    const int mr = hf * 64, n0 = (warp & 3) * 16;
    const uint32_t as_u = smem_u32(As);
    const uint32_t bs_u = smem_u32(Bs + hf * 128 * K2BS);
    const int brow = (lane & 7) + 8 * ((lane >> 3) & 1);
    const int bcol = n0 + 8 * (lane >> 4);
    float acc[4][2][4] = {};

#pragma unroll
    for (int kt = 0; kt < 4; kt++) {
        const int kk = kt * 16;
        uint32_t ah[4][4], al[4][4], bh[4], bl[4];
#pragma unroll
        for (int mt = 0; mt < 4; mt++) {
            uint32_t basea = as_u + (uint32_t)(((mr + mt*16 + lrow) * AK2) + kk + lcol8) * 2;
            ldsm4(ah[mt], basea);
            ldsm4(al[mt], basea + 128);
        }
        ldsm4t(bh, bs_u + (uint32_t)(((kk + brow) * K2BS) + bcol) * 2);
        ldsm4t(bl, bs_u + (uint32_t)(((64 + kk + brow) * K2BS) + bcol) * 2);
        // trans x4 on [k][j]: {r0,r1,r2,r3} = {b0@n0, b1@n0, b0@n0+8, b1@n0+8}
#pragma unroll
        for (int mt = 0; mt < 4; mt++) {
            mma16(acc[mt][0], ah[mt], bh[0], bh[1]);
            mma16(acc[mt][0], ah[mt], bl[0], bl[1]);
            mma16(acc[mt][0], al[mt], bh[0], bh[1]);
            mma16(acc[mt][1], ah[mt], bh[2], bh[3]);
            mma16(acc[mt][1], ah[mt], bl[2], bl[3]);
            mma16(acc[mt][1], al[mt], bh[2], bh[3]);
        }
    }
    __syncthreads();

    uint32_t* Ds = (uint32_t*)smraw;                  // [128][68] packed
    const int g = lane >> 2, t2 = (lane & 3) * 2;
#pragma unroll
    for (int mt = 0; mt < 4; mt++)
#pragma unroll
        for (int nt = 0; nt < 2; nt++) {
            int row = mr + mt*16 + g;
            int jl = (warp & 3) * 16 + nt*8 + t2;
            Ds[row*68 + jl]         = splitpack(acc[mt][nt][0]);
            Ds[row*68 + jl + 1]     = splitpack(acc[mt][nt][1]);
            Ds[(row+8)*68 + jl]     = splitpack(acc[mt][nt][2]);
            Ds[(row+8)*68 + jl + 1] = splitpack(acc[mt][nt][3]);
        }
    __syncthreads();
#pragma unroll
    for (int it = 0; it < 8; it++) {
        int idx = tid + it * 256;
        int row = idx >> 4, j4 = (idx & 15) * 4;
        uint4 v = *(const uint4*)&Ds[row*68 + j4];
        *(uint4*)&g_prod[base + (size_t)row*64 + j4] = v;
    }
}

// ===================== K3 =====================
__global__ __launch_bounds__(256, 2) void k3(const float* __restrict__ SP,
                                             const float* __restrict__ W6,
                                             float* __restrict__ out) {
    extern __shared__ char smraw[];
    unsigned short* As = (unsigned short*)smraw;               // [128][AK2] | pass2 [k=c][m]
    unsigned short* Bs = (unsigned short*)(smraw + 128*AK2*2); // [64][BK3]
    const int tid = threadIdx.x;
    const int row0 = blockIdx.x * 128;
    const int b = row0 >> 12, rig = row0 & 4095;

    const float4* SPg = (const float4*)(SP + (size_t)row0 * 64);
#pragma unroll
    for (int it = 0; it < 8; it++) {
        int idx = tid + it * 256;
        float4 v = SPg[idx];
        int r = idx >> 4, k0 = (idx & 15) * 4;
        unsigned short h0,l0,h1,l1,h2,l2,h3,l3;
        splitb(v.x,h0,l0); splitb(v.y,h1,l1); splitb(v.z,h2,l2); splitb(v.w,h3,l3);
        *(uint2*)&As[r*AK2 + k0]      = make_uint2((uint32_t)h0|((uint32_t)h1<<16), (uint32_t)h2|((uint32_t)h3<<16));
        *(uint2*)&As[r*AK2 + 64 + k0] = make_uint2((uint32_t)l0|((uint32_t)l1<<16), (uint32_t)l2|((uint32_t)l3<<16));
    }
#pragma unroll
    for (int it = 0; it < 8; it++) {
        int idx = tid + it * 256;
        int o = idx >> 5, m0 = (idx & 31) * 4;
        float4 v = ((const float4*)W6)[idx];
        unsigned short h0,l0,h1,l1,h2,l2,h3,l3;
        splitb(v.x,h0,l0); splitb(v.y,h1,l1); splitb(v.z,h2,l2); splitb(v.w,h3,l3);
        int s = (m0 < 64) ? 0 : 136;
        int k0 = m0 & 63;
        *(uint2*)&Bs[o*BK3 + s + k0]      = make_uint2((uint32_t)h0|((uint32_t)h1<<16), (uint32_t)h2|((uint32_t)h3<<16));
        *(uint2*)&Bs[o*BK3 + s + 64 + k0] = make_uint2((uint32_t)l0|((uint32_t)l1<<16), (uint32_t)l2|((uint32_t)l3<<16));
    }
    __syncthreads();

    const int warp = tid >> 5, lane = tid & 31;
    const int lrow = lane & 15, lcol8 = (lane >> 4) * 8;
    const int mr = (warp >> 2) * 64, nc = (warp & 3) * 16;
    const uint32_t as_u = smem_u32(As), bs_u = smem_u32(Bs);
    float acc[4][2][4] = {};

#pragma unroll
    for (int kt = 0; kt < 4; kt++) {                  // pass 1: SP @ W6a^T
        const int kk = kt * 16;
        uint32_t ah[4][4], al[4][4], bh[4], bl[4];
#pragma unroll
        for (int mt = 0; mt < 4; mt++) {
            uint32_t basea = as_u + (uint32_t)(((mr + mt*16 + lrow) * AK2) + kk + lcol8) * 2;
            ldsm4(ah[mt], basea);
            ldsm4(al[mt], basea + 128);
        }
        {
            uint32_t baseb = bs_u + (uint32_t)(((nc + lrow) * BK3) + kk + lcol8) * 2;
            ldsm4(bh, baseb);
            ldsm4(bl, baseb + 128);
        }
        // [n][k] x4: {b0@nc, b0@nc+8, b1@nc, b1@nc+8}
#pragma unroll
        for (int mt = 0; mt < 4; mt++) {
            mma16(acc[mt][0], ah[mt], bh[0], bh[2]);
            mma16(acc[mt][0], ah[mt], bl[0], bl[2]);
            mma16(acc[mt][0], al[mt], bh[0], bh[2]);
            mma16(acc[mt][1], ah[mt], bh[1], bh[3]);
            mma16(acc[mt][1], ah[mt], bl[1], bl[3]);
            mma16(acc[mt][1], al[mt], bh[1], bh[3]);
        }
    }
    __syncthreads();

    // restage A = prod in [k=c][m] layout: rows 0-63 hi, 64-127 lo
#pragma unroll
    for (int it = 0; it < 8; it++) {
        int idx = tid + it * 256;
        int e0 = idx * 4;
        int m0 = e0 & 127, c = e0 >> 7;
        uint4 p = *(const uint4*)&g_prod[(size_t)(b*64 + c)*4096 + rig + m0];
        *(uint2*)&As[c*AK2 + m0]        = make_uint2(prmt(p.x,p.y,0x5410), prmt(p.z,p.w,0x5410));
        *(uint2*)&As[(64+c)*AK2 + m0]   = make_uint2(prmt(p.x,p.y,0x7632), prmt(p.z,p.w,0x7632));
    }
    __syncthreads();

    // pass 2: + prod @ W6b^T.  A via ldmatrix.trans from [k=c][m] storage.
    const int arow = (lane & 7) + 8 * (lane >> 4);
    const int acol8 = 8 * ((lane >> 3) & 1);
#pragma unroll
    for (int kt = 0; kt < 4; kt++) {
        const int kk = kt * 16;
        uint32_t ah[4][4], al[4][4], bh[4], bl[4];
#pragma unroll
        for (int mt = 0; mt < 4; mt++) {
            ldsm4t(ah[mt], as_u + (uint32_t)(((kk + arow) * AK2) + mr + mt*16 + acol8) * 2);
            ldsm4t(al[mt], as_u + (uint32_t)(((64 + kk + arow) * AK2) + mr + mt*16 + acol8) * 2);
        }
        {
            uint32_t baseb = bs_u + (uint32_t)(((nc + lrow) * BK3) + 136 + kk + lcol8) * 2;
            ldsm4(bh, baseb);
            ldsm4(bl, baseb + 128);
        }
#pragma unroll
        for (int mt = 0; mt < 4; mt++) {
            mma16(acc[mt][0], ah[mt], bh[0], bh[2]);
            mma16(acc[mt][0], ah[mt], bl[0], bl[2]);
            mma16(acc[mt][0], al[mt], bh[0], bh[2]);
            mma16(acc[mt][1], ah[mt], bh[1], bh[3]);
            mma16(acc[mt][1], ah[mt], bl[1], bl[3]);
            mma16(acc[mt][1], al[mt], bh[1], bh[3]);
        }
    }
    __syncthreads();

    float* Ds = (float*)smraw;                        // [128][68]
    const int g = lane >> 2, t2 = (lane & 3) * 2;
#pragma unroll
    for (int mt = 0; mt < 4; mt++)
#pragma unroll
        for (int nt = 0; nt < 2; nt++) {
            int row = mr + mt*16 + g;
            int col = nc + nt*8 + t2;
            Ds[row*68 + col]         = fmaxf(acc[mt][nt][0], 0.f);
            Ds[row*68 + col + 1]     = fmaxf(acc[mt][nt][1], 0.f);
            Ds[(row+8)*68 + col]     = fmaxf(acc[mt][nt][2], 0.f);
            Ds[(row+8)*68 + col + 1] = fmaxf(acc[mt][nt][3], 0.f);
        }
    __syncthreads();
    float* ob = out + (size_t)row0 * 64;
#pragma unroll
    for (int it = 0; it < 8; it++) {
        int idx = tid + it * 256;
        int m = idx >> 4, o4 = (idx & 15) * 4;
        *(float4*)&ob[m*64 + o4] = *(const float4*)&Ds[m*68 + o4];
    }
}

// ---------------------------------------------------------------------------
extern "C" void kernel_launch(void* const* d_in, const int* in_sizes, int n_in,
                              void* d_out, int out_size) {
    const float* SP = nullptr; const float* W4 = nullptr;
    const float* W5 = nullptr; const float* W6 = nullptr;
    for (int i = 0; i < n_in; i++) {
        int sz = in_sizes[i];
        if (sz == 67108864)      SP = (const float*)d_in[i];
        else if (sz == 8192)     W6 = (const float*)d_in[i];
        else if (sz == 4096)     { if (!W4) W4 = (const float*)d_in[i]; else W5 = (const float*)d_in[i]; }
    }
    float* out = (float*)d_out;

    const int smem1 = 2 * (128 * AK2) * 2;                      // 69632
    const int smem2 = (128 * AK2) * 2 + 2 * (128 * K2BS) * 2;   // 71680
    const int smem3 = (128 * AK2) * 2 + (64 * BK3) * 2;         // 70656
    cudaFuncSetAttribute(k1, cudaFuncAttributeMaxDynamicSharedMemorySize, smem1);
    cudaFuncSetAttribute(k2, cudaFuncAttributeMaxDynamicSharedMemorySize, smem2);
    cudaFuncSetAttribute(k3, cudaFuncAttributeMaxDynamicSharedMemorySize, smem3);

    k1<<<8192, 256, smem1>>>(SP, W4, W5);
    k2<<<8192, 256, smem2>>>();
    k3<<<8192, 256, smem3>>>(SP, W6, out);
}